// round 1
// baseline (speedup 1.0000x reference)
#include <cuda_runtime.h>
#include <cuda_bf16.h>

#define NX 1024
#define NY 1024
#define DIMK 128

// Scratch (device globals — allocation-free per harness rules)
__device__ float        g_s[NX * NY];        // 4 MB distance matrix (L2-resident)
__device__ unsigned int g_rmax_bits[NX];     // uint-encoded row max of s (s<=0: max == uint-min of bits)
__device__ unsigned int g_cmax_bits[NY];
__device__ float        g_rsum[NX];          // row sumexp, later inverted in place
__device__ float        g_csum[NY];          // col sumexp (atomic accum), later inverted
__device__ double       g_S1, g_S2;

// ---------------------------------------------------------------- K0: init
__global__ void k_init() {
    int t = blockIdx.x * blockDim.x + threadIdx.x;
    if (t < NX) g_rmax_bits[t] = 0xFFFFFFFFu;
    if (t < NY) { g_cmax_bits[t] = 0xFFFFFFFFu; g_csum[t] = 0.0f; }
    if (t == 0) { g_S1 = 0.0; g_S2 = 0.0; }
}

// ---------------------------------------------------------------- K1: distances
// 64x64 tile per block, 256 threads, 4x4 register micro-tile per thread.
// Shared layout: [row][64 d-chunk] pitch 68 floats; float4 groups XOR-swizzled
// by (row>>2)&15 so inner reads are ~2-phase.
#define TP 68
__global__ __launch_bounds__(256)
void k_dist(const float* __restrict__ zx, const float* __restrict__ zy) {
    __shared__ float xs[64 * TP];
    __shared__ float ys[64 * TP];
    __shared__ float red[16 * 65];

    int tid = threadIdx.x;
    int tx = tid & 15, ty = tid >> 4;
    int bi = blockIdx.y << 6, bj = blockIdx.x << 6;

    float acc[4][4];
#pragma unroll
    for (int i = 0; i < 4; i++)
#pragma unroll
        for (int j = 0; j < 4; j++) acc[i][j] = 0.0f;

    for (int kc = 0; kc < 2; kc++) {
        if (kc) __syncthreads();
        // stage 64 rows x 64 d's of each operand
#pragma unroll
        for (int l = tid; l < 1024; l += 256) {
            int r  = l >> 4;
            int dq = l & 15;
            int sw = (dq ^ ((r >> 2) & 15)) << 2;
            float4 vx = *reinterpret_cast<const float4*>(zx + (bi + r) * DIMK + kc * 64 + dq * 4);
            *reinterpret_cast<float4*>(&xs[r * TP + sw]) = vx;
            float4 vy = *reinterpret_cast<const float4*>(zy + (bj + r) * DIMK + kc * 64 + dq * 4);
            *reinterpret_cast<float4*>(&ys[r * TP + sw]) = vy;
        }
        __syncthreads();

#pragma unroll 4
        for (int dq = 0; dq < 16; dq++) {
            float4 av[4], bv[4];
            int gx = (dq ^ ty) << 2;   // xs swizzle mask = (row>>2) = ty for rows 4ty..4ty+3
            int gy = (dq ^ tx) << 2;   // ys swizzle mask = tx
#pragma unroll
            for (int ii = 0; ii < 4; ii++)
                av[ii] = *reinterpret_cast<const float4*>(&xs[(4 * ty + ii) * TP + gx]);
#pragma unroll
            for (int jj = 0; jj < 4; jj++)
                bv[jj] = *reinterpret_cast<const float4*>(&ys[(4 * tx + jj) * TP + gy]);
#pragma unroll
            for (int ii = 0; ii < 4; ii++)
#pragma unroll
                for (int jj = 0; jj < 4; jj++) {
                    acc[ii][jj] += fabsf(av[ii].x - bv[jj].x);
                    acc[ii][jj] += fabsf(av[ii].y - bv[jj].y);
                    acc[ii][jj] += fabsf(av[ii].z - bv[jj].z);
                    acc[ii][jj] += fabsf(av[ii].w - bv[jj].w);
                }
        }
    }

    // write s = -acc (coalesced float4)
#pragma unroll
    for (int ii = 0; ii < 4; ii++) {
        float4 v = make_float4(-acc[ii][0], -acc[ii][1], -acc[ii][2], -acc[ii][3]);
        *reinterpret_cast<float4*>(&g_s[(bi + 4 * ty + ii) * NY + bj + 4 * tx]) = v;
    }

    // --- partial row maxes (min of acc over the tile's 64 cols) ---
    __syncthreads();
#pragma unroll
    for (int ii = 0; ii < 4; ii++) {
        float m = fminf(fminf(acc[ii][0], acc[ii][1]), fminf(acc[ii][2], acc[ii][3]));
        red[tx * 65 + 4 * ty + ii] = m;
    }
    __syncthreads();
    if (tid < 64) {
        float m = red[tid];
#pragma unroll
        for (int x = 1; x < 16; x++) m = fminf(m, red[x * 65 + tid]);
        atomicMin(&g_rmax_bits[bi + tid], __float_as_uint(-m));
    }
    __syncthreads();
    // --- partial col maxes ---
#pragma unroll
    for (int jj = 0; jj < 4; jj++) {
        float m = fminf(fminf(acc[0][jj], acc[1][jj]), fminf(acc[2][jj], acc[3][jj]));
        red[ty * 65 + 4 * tx + jj] = m;
    }
    __syncthreads();
    if (tid < 64) {
        float m = red[tid];
#pragma unroll
        for (int x = 1; x < 16; x++) m = fminf(m, red[x * 65 + tid]);
        atomicMin(&g_cmax_bits[bj + tid], __float_as_uint(-m));
    }
}

// ---------------------------------------------------------------- reductions
__device__ __forceinline__ float warp_sum(float v) {
#pragma unroll
    for (int o = 16; o > 0; o >>= 1) v += __shfl_xor_sync(0xFFFFFFFFu, v, o);
    return v;
}

// K2a: one block per row -> rsum[i]
__global__ __launch_bounds__(256) void k_row() {
    int i = blockIdx.x;
    int tid = threadIdx.x;
    float rmax = __uint_as_float(g_rmax_bits[i]);
    float4 s4 = *reinterpret_cast<const float4*>(&g_s[i * NY + 4 * tid]);
    float p = __expf(s4.x - rmax) + __expf(s4.y - rmax) +
              __expf(s4.z - rmax) + __expf(s4.w - rmax);
    __shared__ float sh[8];
    int lane = tid & 31, w = tid >> 5;
    p = warp_sum(p);
    if (lane == 0) sh[w] = p;
    __syncthreads();
    if (w == 0) {
        p = (lane < 8) ? sh[lane] : 0.0f;
        p = warp_sum(p);
        if (lane == 0) g_rsum[i] = p;
    }
}

// K2b: cols, tiled 32 cols x 128 rows per block, atomicAdd partials
__global__ __launch_bounds__(256) void k_col() {
    int tx = threadIdx.x & 31, ty = threadIdx.x >> 5;
    int j  = blockIdx.x * 32 + tx;
    int r0 = blockIdx.y * 128;
    float cmax = __uint_as_float(g_cmax_bits[j]);
    float p = 0.0f;
#pragma unroll 4
    for (int i = r0 + ty; i < r0 + 128; i += 8)
        p += __expf(g_s[i * NY + j] - cmax);
    __shared__ float sh[8][32];
    sh[ty][tx] = p;
    __syncthreads();
    if (ty == 0) {
        float t = 0.0f;
#pragma unroll
        for (int k = 0; k < 8; k++) t += sh[k][tx];
        atomicAdd(&g_csum[j], t);
    }
}

// K2c: invert sums in place
__global__ void k_inv() {
    int t = blockIdx.x * blockDim.x + threadIdx.x;
    if (t < NX) g_rsum[t] = 1.0f / g_rsum[t];
    if (t < NY) g_csum[t] = 1.0f / g_csum[t];
}

// K3: one block per row; a = er + ec - er*ec; accumulate S1 = sum a, S2 = sum a*s
__global__ __launch_bounds__(256) void k_final() {
    int i = blockIdx.x;
    int tid = threadIdx.x;
    float rmax = __uint_as_float(g_rmax_bits[i]);
    float rinv = g_rsum[i];

    float4 s4 = *reinterpret_cast<const float4*>(&g_s[i * NY + 4 * tid]);
    uint4  cb = *reinterpret_cast<const uint4*>(&g_cmax_bits[4 * tid]);
    float4 ci = *reinterpret_cast<const float4*>(&g_csum[4 * tid]);

    float p1 = 0.0f, p2 = 0.0f;
    {
        float er = __expf(s4.x - rmax) * rinv;
        float ec = __expf(s4.x - __uint_as_float(cb.x)) * ci.x;
        float a = er + ec - er * ec; p1 += a; p2 += a * s4.x;
    }
    {
        float er = __expf(s4.y - rmax) * rinv;
        float ec = __expf(s4.y - __uint_as_float(cb.y)) * ci.y;
        float a = er + ec - er * ec; p1 += a; p2 += a * s4.y;
    }
    {
        float er = __expf(s4.z - rmax) * rinv;
        float ec = __expf(s4.z - __uint_as_float(cb.z)) * ci.z;
        float a = er + ec - er * ec; p1 += a; p2 += a * s4.z;
    }
    {
        float er = __expf(s4.w - rmax) * rinv;
        float ec = __expf(s4.w - __uint_as_float(cb.w)) * ci.w;
        float a = er + ec - er * ec; p1 += a; p2 += a * s4.w;
    }

    __shared__ float sh1[8], sh2[8];
    int lane = tid & 31, w = tid >> 5;
    p1 = warp_sum(p1);
    p2 = warp_sum(p2);
    if (lane == 0) { sh1[w] = p1; sh2[w] = p2; }
    __syncthreads();
    if (w == 0) {
        p1 = (lane < 8) ? sh1[lane] : 0.0f;
        p2 = (lane < 8) ? sh2[lane] : 0.0f;
        p1 = warp_sum(p1);
        p2 = warp_sum(p2);
        if (lane == 0) {
            atomicAdd(&g_S1, (double)p1);
            atomicAdd(&g_S2, (double)p2);
        }
    }
}

// K4: logits = c*theta + beta
__global__ void k_out(const float* __restrict__ theta, const float* __restrict__ beta,
                      float* __restrict__ out, int n) {
    int t = threadIdx.x;
    if (t < n) {
        float c = (float)(g_S2 / g_S1);
        out[t] = c * theta[t] + beta[t];
    }
}

// ---------------------------------------------------------------- launch
extern "C" void kernel_launch(void* const* d_in, const int* in_sizes, int n_in,
                              void* d_out, int out_size) {
    (void)n_in;
    const float* zx    = (const float*)d_in[0];
    const float* zy    = (const float*)d_in[1];
    const float* theta = (const float*)d_in[2];
    const float* beta  = (const float*)d_in[3];
    float* out = (float*)d_out;

    k_init<<<4, 256>>>();
    dim3 g1(NY / 64, NX / 64);
    k_dist<<<g1, 256>>>(zx, zy);
    k_row<<<NX, 256>>>();
    k_col<<<dim3(NY / 32, NX / 128), 256>>>();
    k_inv<<<4, 256>>>();
    k_final<<<NX, 256>>>();
    k_out<<<1, 32>>>(theta, beta, out, out_size);
    (void)in_sizes;
}